// round 17
// baseline (speedup 1.0000x reference)
#include <cuda_runtime.h>
#include <cuda_bf16.h>
#include <cuda_fp16.h>
#include <cstdint>
#include <cstddef>

// ---------------------------------------------------------------------------
// WindowAttention (Swin-style): B_=4096 windows, N=49, C=384, H=12, hd=32
// Round 17: GEMM tile 256x128 (512 threads, warp 32x64) — halves SMEM
//           bytes/FLOP (crossbar-bound). Attention unchanged from R16.
// ---------------------------------------------------------------------------

#define B_WIN   4096
#define N_TOK   49
#define DIM     384
#define H_HEADS 12
#define HD      32
#define T_TOT   (B_WIN * N_TOK)      // 200704 tokens
#define NW_MASK 64
#define NN      (N_TOK * N_TOK)      // 2401
#define WHD     (N_TOK * HD)         // 1568 halves per (mtx,h,b)

__device__ __half g_qkvh[(size_t)3 * H_HEADS * B_WIN * WHD]; // permuted qkv
__device__ __half g_aoh [(size_t)T_TOT * DIM];      // (T, 384) fp16
__device__ __half g_xh  [(size_t)T_TOT * DIM];      // x, fp16
__device__ __half g_wh  [3 * DIM * DIM + DIM * DIM];// qkv_w | proj_w fp16
__device__ float  g_comb[(size_t)H_HEADS * NW_MASK * NN];  // bias+mask

// ---------------------------------------------------------------------------
// helpers
// ---------------------------------------------------------------------------
__device__ __forceinline__ void mma_f16_16x8x16(float d[4], const uint32_t a[4],
                                                const uint32_t b[2]) {
    asm volatile(
        "mma.sync.aligned.m16n8k16.row.col.f32.f16.f16.f32 "
        "{%0,%1,%2,%3}, {%4,%5,%6,%7}, {%8,%9}, {%0,%1,%2,%3};\n"
        : "+f"(d[0]), "+f"(d[1]), "+f"(d[2]), "+f"(d[3])
        : "r"(a[0]), "r"(a[1]), "r"(a[2]), "r"(a[3]), "r"(b[0]), "r"(b[1]));
}

__device__ __forceinline__ void ldsm_x4(uint32_t& r0, uint32_t& r1,
                                        uint32_t& r2, uint32_t& r3, uint32_t addr) {
    asm volatile("ldmatrix.sync.aligned.m8n8.x4.shared.b16 {%0,%1,%2,%3}, [%4];\n"
                 : "=r"(r0), "=r"(r1), "=r"(r2), "=r"(r3) : "r"(addr));
}

__device__ __forceinline__ void ldsm_x4t(uint32_t& r0, uint32_t& r1,
                                         uint32_t& r2, uint32_t& r3, uint32_t addr) {
    asm volatile("ldmatrix.sync.aligned.m8n8.x4.trans.shared.b16 {%0,%1,%2,%3}, [%4];\n"
                 : "=r"(r0), "=r"(r1), "=r"(r2), "=r"(r3) : "r"(addr));
}

__device__ __forceinline__ void ldsm_x2(uint32_t& r0, uint32_t& r1, uint32_t addr) {
    asm volatile("ldmatrix.sync.aligned.m8n8.x2.shared.b16 {%0,%1}, [%2];\n"
                 : "=r"(r0), "=r"(r1) : "r"(addr));
}

__device__ __forceinline__ void cp_async16(uint32_t smem_addr, const void* gptr) {
    asm volatile("cp.async.cg.shared.global [%0], [%1], 16;\n"
                 :: "r"(smem_addr), "l"(gptr) : "memory");
}

// ---------------------------------------------------------------------------
// Kernel R: convert fp32 -> fp16 (RN)
// ---------------------------------------------------------------------------
__global__ void f32_to_f16_kernel(const float* __restrict__ src,
                                  __half* __restrict__ dst, int n4) {
    int i = blockIdx.x * blockDim.x + threadIdx.x;
    int stride = gridDim.x * blockDim.x;
    for (; i < n4; i += stride) {
        float4 v = ((const float4*)src)[i];
        __half2 h01 = __floats2half2_rn(v.x, v.y);
        __half2 h23 = __floats2half2_rn(v.z, v.w);
        uint2 o;
        o.x = *(uint32_t*)&h01;
        o.y = *(uint32_t*)&h23;
        ((uint2*)dst)[i] = o;
    }
}

// ---------------------------------------------------------------------------
// Kernel 0: comb[h][w][n][m] = bias_table[rel_index[n,m]][h] + mask[w][n][m]
// ---------------------------------------------------------------------------
__global__ void comb_kernel(const float* __restrict__ bias_table,
                            const int* __restrict__ rel_index,
                            const float* __restrict__ mask) {
    int idx = blockIdx.x * blockDim.x + threadIdx.x;
    if (idx < H_HEADS * NW_MASK * NN) {
        int h   = idx / (NW_MASK * NN);
        int rem = idx - h * (NW_MASK * NN);
        int w   = rem / NN;
        int nm  = rem - w * NN;
        g_comb[idx] = bias_table[rel_index[nm] * H_HEADS + h] + mask[w * NN + nm];
    }
}

// ---------------------------------------------------------------------------
// Kernel 1/3: fp16 GEMM  C[m,n] = sum_k A[m,k]*B[n,k] + bias[n]
//   BM=256, BN=128, BK=64 halves; 512 threads (16 warps, 8x2, warp 32x64).
//   2-stage cp.async, XOR-swizzled SMEM, ldmatrix. 96 KB SMEM, 1 CTA/SM.
// ---------------------------------------------------------------------------
#define GBM 256
#define GBN 128
#define GBK 64
#define GSTG_A (GBM * GBK * 2)                // 32768 bytes
#define GSTG_B (GBN * GBK * 2)                // 16384 bytes
#define GEMM_SMEM_BYTES (2 * (GSTG_A + GSTG_B))   // 98304

template <bool QKV_OUT>
__global__ __launch_bounds__(512, 1)
void gemm_f16_pipe(const __half* __restrict__ A, const __half* __restrict__ B,
                   const float* __restrict__ bias, void* __restrict__ Cv,
                   int M, int N, int K) {
    extern __shared__ float dynsmem[];
    const uint32_t as_base = (uint32_t)__cvta_generic_to_shared(dynsmem);
    const uint32_t bs_base = as_base + 2 * GSTG_A;

    const int tid  = threadIdx.x;
    const int lane = tid & 31;
    const int warp = tid >> 5;          // 0..15
    const int wm   = warp >> 1;         // 0..7 (32 rows each)
    const int wn   = warp & 1;          // 0..1 (64 cols each)
    const int bm   = blockIdx.y * GBM;
    const int bn   = blockIdx.x * GBN;
    const int r4   = lane >> 2;
    const int c4   = lane & 3;

    const int lc4  = tid & 7;
    const int lrow = tid >> 3;          // 0..63
    const int pc4  = lc4 ^ (lrow & 7);

    const int l7       = lane & 7;
    const int a_half_m = (lane >> 3) & 1;
    const int b_sel    = lane >> 4;

    int rA7[2]; uint32_t baseA[2];
    #pragma unroll
    for (int mt = 0; mt < 2; mt++) {
        int row = wm * 32 + mt * 16 + a_half_m * 8 + l7;
        rA7[mt]   = row & 7;
        baseA[mt] = (uint32_t)row * 128;
    }
    int rB7[4]; uint32_t baseB[4];
    #pragma unroll
    for (int j = 0; j < 4; j++) {
        int row = wn * 64 + (2 * j + b_sel) * 8 + l7;
        rB7[j]   = row & 7;
        baseB[j] = (uint32_t)row * 128;
    }
    const int a_half_k = lane >> 4;
    const int b_half_k = (lane >> 3) & 1;

    const int kTiles = K / GBK;

    auto issue = [&](int ktf, int s) {
        #pragma unroll
        for (int i = 0; i < 4; i++) {
            int r = lrow + i * 64;
            cp_async16(as_base + (uint32_t)(s * GSTG_A + r * 128 + pc4 * 16),
                       A + (size_t)(bm + r) * K + ktf + lc4 * 8);
        }
        #pragma unroll
        for (int i = 0; i < 2; i++) {
            int r = lrow + i * 64;
            cp_async16(bs_base + (uint32_t)(s * GSTG_B + r * 128 + pc4 * 16),
                       B + (size_t)(bn + r) * K + ktf + lc4 * 8);
        }
        asm volatile("cp.async.commit_group;\n" ::: "memory");
    };

    float acc[2][8][4];
    #pragma unroll
    for (int mt = 0; mt < 2; mt++)
        #pragma unroll
        for (int nt = 0; nt < 8; nt++)
            #pragma unroll
            for (int i = 0; i < 4; i++) acc[mt][nt][i] = 0.f;

    issue(0, 0);

    for (int t = 0; t < kTiles; t++) {
        const int s = t & 1;
        if (t + 1 < kTiles) {
            issue((t + 1) * GBK, s ^ 1);
            asm volatile("cp.async.wait_group 1;\n" ::: "memory");
        } else {
            asm volatile("cp.async.wait_group 0;\n" ::: "memory");
        }
        __syncthreads();

        const uint32_t asb = as_base + (uint32_t)(s * GSTG_A);
        const uint32_t bsb = bs_base + (uint32_t)(s * GSTG_B);
        #pragma unroll
        for (int step = 0; step < 4; step++) {
            const int kk = step * 2;
            uint32_t af[2][4];
            uint32_t bf[8][2];
            #pragma unroll
            for (int mt = 0; mt < 2; mt++) {
                uint32_t addr = asb + baseA[mt] +
                                (uint32_t)(((kk + a_half_k) ^ rA7[mt]) << 4);
                ldsm_x4(af[mt][0], af[mt][1], af[mt][2], af[mt][3], addr);
            }
            #pragma unroll
            for (int j = 0; j < 4; j++) {
                uint32_t addr = bsb + baseB[j] +
                                (uint32_t)(((kk + b_half_k) ^ rB7[j]) << 4);
                ldsm_x4(bf[2 * j][0], bf[2 * j][1], bf[2 * j + 1][0], bf[2 * j + 1][1], addr);
            }
            #pragma unroll
            for (int mt = 0; mt < 2; mt++)
                #pragma unroll
                for (int nt = 0; nt < 8; nt++)
                    mma_f16_16x8x16(acc[mt][nt], af[mt], bf[nt]);
        }
        __syncthreads();
    }

    // epilogue
    const float qsc = 0.1767766952966369f;   // 32^-0.5
    #pragma unroll
    for (int mt = 0; mt < 2; mt++) {
        int row0 = bm + wm * 32 + mt * 16 + r4;
        if (QKV_OUT) {
            __half* C = (__half*)Cv;
            int t0 = row0, t1 = row0 + 8;
            int b0q = t0 / N_TOK, n0q = t0 - b0q * N_TOK;
            int b1q = t1 / N_TOK, n1q = t1 - b1q * N_TOK;
            #pragma unroll
            for (int nt = 0; nt < 8; nt++) {
                int col = bn + wn * 64 + nt * 8 + 2 * c4;
                int mtx = col / DIM;
                int rem = col - mtx * DIM;
                int hh  = rem >> 5;
                int dd  = rem & 31;
                float sc = (mtx == 0) ? qsc : 1.f;
                float bb0 = bias[col], bb1 = bias[col + 1];
                __half* base = C + (size_t)(mtx * H_HEADS + hh) * B_WIN * WHD + dd;
                *(__half2*)(base + ((size_t)b0q * N_TOK + n0q) * HD) =
                    __floats2half2_rn((acc[mt][nt][0] + bb0) * sc,
                                      (acc[mt][nt][1] + bb1) * sc);
                *(__half2*)(base + ((size_t)b1q * N_TOK + n1q) * HD) =
                    __floats2half2_rn((acc[mt][nt][2] + bb0) * sc,
                                      (acc[mt][nt][3] + bb1) * sc);
            }
        } else {
            float* C = (float*)Cv;
            #pragma unroll
            for (int nt = 0; nt < 8; nt++) {
                int col = bn + wn * 64 + nt * 8 + 2 * c4;
                float bb0 = bias[col], bb1 = bias[col + 1];
                *(float2*)(C + (size_t)row0 * N + col) =
                    make_float2(acc[mt][nt][0] + bb0, acc[mt][nt][1] + bb1);
                *(float2*)(C + (size_t)(row0 + 8) * N + col) =
                    make_float2(acc[mt][nt][2] + bb0, acc[mt][nt][3] + bb1);
            }
        }
    }
}

// ---------------------------------------------------------------------------
// Kernel 2: fused attention, looped windows w/ cp.async (unchanged from R16)
// ---------------------------------------------------------------------------
#define QSTRH 40
#define PSTRH 72
#define W_QK  (N_TOK * QSTRH)       // 1960 halves
#define W_V   (64 * QSTRH)          // 2560 halves (rows 49..63 zero)
#define W_BUF (2 * W_QK + W_V)      // 6480 halves per window buffer
#define HS_BUFS (4 * W_BUF)         // 2 stages x 2 windows
#define W_P   (N_TOK * PSTRH)       // 3528
#define HS_P  HS_BUFS
#define HS_TOT (HS_BUFS + 2 * W_P)
#define ATTN_SMEM_BYTES (HS_TOT * 2 + NN * 4)   // 75556
#define AITERS 8

__global__ __launch_bounds__(256)
void attn_loop_kernel() {
    extern __shared__ __align__(16) char smraw[];
    __half* hs = (__half*)smraw;
    float*  cb = (float*)(smraw + HS_TOT * 2);
    const uint32_t hs_u = (uint32_t)__cvta_generic_to_shared(hs);

    const int h    = blockIdx.x;
    const int w    = blockIdx.y;
    const int z    = blockIdx.z;
    const int tid  = threadIdx.x;
    const int wg   = tid >> 7;
    const int lane = tid & 31;
    const int warp = (tid >> 5) & 3;
    const int r4   = lane >> 2;
    const int c4   = lane & 3;
    const int l7   = lane & 7;
    const int g8   = (lane >> 3) & 1;
    const int g16  = lane >> 4;

    for (int i = tid; i < 4 * 60; i += 256) {
        int buf = i / 60, r = i % 60;
        __half* v = hs + buf * W_BUF + 2 * W_QK;
        *(uint4*)&v[(49 + (r >> 2)) * QSTRH + (r & 3) * 8] = make_uint4(0, 0, 0, 0);
    }
    for (int i = tid; i < 2 * 98; i += 256) {
        int ww = i / 98, r = i % 98;
        __half* P = hs + HS_P + ww * W_P;
        *(uint4*)&P[(r >> 1) * PSTRH + 48 + (r & 1) * 8] = make_uint4(0, 0, 0, 0);
    }
    {
        const float* cbg = g_comb + (size_t)(h * NW_MASK + w) * NN;
        for (int i = tid; i < NN; i += 256) cb[i] = cbg[i];
    }

    auto issue = [&](int it, int s) {
        #pragma unroll 5
        for (int idx = tid; idx < 1176; idx += 256) {
            int wslot = idx / 588;
            int r     = idx - wslot * 588;
            int mat   = r / 196;
            int g     = r - mat * 196;
            int bw    = w + NW_MASK * (z * (2 * AITERS) + 2 * it + wslot);
            const __half* src = g_qkvh + (size_t)mat * H_HEADS * B_WIN * WHD
                              + ((size_t)h * B_WIN + bw) * WHD + g * 8;
            uint32_t dst = hs_u + (uint32_t)((s * 2 + wslot) * W_BUF + mat * W_QK) * 2
                         + (uint32_t)((g >> 2) * QSTRH + (g & 3) * 8) * 2;
            cp_async16(dst, src);
        }
        asm volatile("cp.async.commit_group;\n" ::: "memory");
    };

    issue(0, 0);

    const int am = warp * 16;

    for (int it = 0; it < AITERS; it++) {
        const int s = it & 1;
        if (it + 1 < AITERS) {
            issue(it + 1, s ^ 1);
            asm volatile("cp.async.wait_group 1;\n" ::: "memory");
        } else {
            asm volatile("cp.async.wait_group 0;\n" ::: "memory");
        }
        __syncthreads();

        const int b = w + NW_MASK * (z * (2 * AITERS) + 2 * it + wg);
        __half* qsw = hs + (s * 2 + wg) * W_BUF;
        __half* ksw = qsw + W_QK;
        __half* vsw = qsw + 2 * W_QK;
        __half* Psw = hs + HS_P + wg * W_P;
        const uint32_t qsu = (uint32_t)__cvta_generic_to_shared(qsw);
        const uint32_t ksu = (uint32_t)__cvta_generic_to_shared(ksw);
        const uint32_t vsu = (uint32_t)__cvta_generic_to_shared(vsw);
        const uint32_t psu = (uint32_t)__cvta_generic_to_shared(Psw);

        {
            float acc[7][4];
            #pragma unroll
            for (int nt = 0; nt < 7; nt++)
                #pragma unroll
                for (int i = 0; i < 4; i++) acc[nt][i] = 0.f;

            const uint32_t aBase = qsu + (uint32_t)min(am + g8 * 8 + l7, N_TOK - 1) * 80
                                 + (uint32_t)g16 * 16;
            uint32_t bBase[3];
            #pragma unroll
            for (int j = 0; j < 3; j++)
                bBase[j] = ksu + (uint32_t)min((2 * j + g16) * 8 + l7, N_TOK - 1) * 80
                         + (uint32_t)g8 * 16;
            const uint32_t bBase6 = ksu + (uint32_t)(N_TOK - 1) * 80 + (uint32_t)g8 * 16;

            #pragma unroll
            for (int sk = 0; sk < 2; sk++) {
                uint32_t af[4], bf[7][2];
                ldsm_x4(af[0], af[1], af[2], af[3], aBase + sk * 32);
                #pragma unroll
                for (int j = 0; j < 3; j++)
                    ldsm_x4(bf[2 * j][0], bf[2 * j][1], bf[2 * j + 1][0], bf[2 * j + 1][1],
                            bBase[j] + sk * 32);
                ldsm_x2(bf[6][0], bf[6][1], bBase6 + sk * 32);
                #pragma unroll
                for (int nt = 0; nt < 7; nt++)
                    mma_f16_16x8x16(acc[nt], af, bf[nt]);
            }

            const int n0  = am + r4;
            const int n1  = n0 + 8;
            const int cr0 = min(n0, N_TOK - 1) * N_TOK;
            const int cr1 = min(n1, N_TOK - 1) * N_TOK;
            float s0 = 0.f, s1 = 0.f;
            #pragma unroll
            for (int nt = 0; nt < 7; nt++) {
                int col0 = nt * 8 + 2 * c4;
                int col1 = col0 + 1;
                float e00 = (col0 < N_TOK) ? __expf(acc[nt][0] + cb[cr0 + col0]) : 0.f;
                float e01 = (col1 < N_TOK) ? __expf(acc[nt][1] + cb[cr0 + col1]) : 0.f;
                float e10 = (col0 < N_TOK) ? __expf(acc[nt][2] + cb[cr1 + col0]) : 0.f;
                float e11 = (col1 < N_TOK) ? __expf(acc[nt][3] + cb[cr1 + col1]) : 0.f;
                acc[nt][0] = e00; acc[nt][1] = e01; acc[nt][2] = e10; acc[nt][3] = e11;
                s0 += e00 + e01;
                s1 += e10 + e11;
            }
            s0 += __shfl_xor_sync(0xffffffffu, s0, 1);
            s0 += __shfl_xor_sync(0xffffffffu, s0, 2);
            s1 += __shfl_xor_sync(0xffffffffu, s1, 1);
            s1 += __shfl_xor_sync(0xffffffffu, s1, 2);
            float inv0 = __frcp_rn(s0);
            float inv1 = __frcp_rn(s1);

            #pragma unroll
            for (int nt = 0; nt < 7; nt++) {
                int col0 = nt * 8 + 2 * c4;
                int col1 = col0 + 1;
                if (col0 < N_TOK) {
                    float p01 = (col1 < N_TOK) ? acc[nt][1] * inv0 : 0.f;
                    float p11 = (col1 < N_TOK) ? acc[nt][3] * inv1 : 0.f;
                    if (n0 < N_TOK)
                        *(__half2*)&Psw[n0 * PSTRH + col0] =
                            __floats2half2_rn(acc[nt][0] * inv0, p01);
                    if (n1 < N_TOK)
                        *(__half2*)&Psw[n1 * PSTRH + col0] =
                            __floats2half2_rn(acc[nt][2] * inv1, p11);
                }
            }
        }
        __syncthreads();

        {
            float acc[4][4];
            #pragma unroll
            for (int nt = 0; nt < 4; nt++)
                #pragma unroll
                for (int i = 0; i < 4; i++) acc[nt][i] = 0.f;

            const uint32_t paBase = psu + (uint32_t)min(am + g8 * 8 + l7, N_TOK - 1) * 144
                                  + (uint32_t)g16 * 16;
            const uint32_t vbBase = vsu + (uint32_t)(g8 * 8 + l7) * 80
                                  + (uint32_t)g16 * 16;

            #pragma unroll
            for (int sk = 0; sk < 4; sk++) {
                uint32_t af[4], bf[4][2];
                ldsm_x4(af[0], af[1], af[2], af[3], paBase + sk * 32);
                ldsm_x4t(bf[0][0], bf[0][1], bf[1][0], bf[1][1], vbBase + sk * 1280);
                ldsm_x4t(bf[2][0], bf[2][1], bf[3][0], bf[3][1], vbBase + sk * 1280 + 32);
                #pragma unroll
                for (int nt = 0; nt < 4; nt++)
                    mma_f16_16x8x16(acc[nt], af, bf[nt]);
            }
            __half* aob = g_aoh + (size_t)b * N_TOK * DIM + h * HD;
            const int n0 = am + r4, n1 = n0 + 8;
            #pragma unroll
            for (int nt = 0; nt < 4; nt++) {
                int col = nt * 8 + 2 * c4;
                if (n0 < N_TOK)
                    *(__half2*)(aob + (size_t)n0 * DIM + col) =
                        __floats2half2_rn(acc[nt][0], acc[nt][1]);
                if (n1 < N_TOK)
                    *(__half2*)(aob + (size_t)n1 * DIM + col) =
                        __floats2half2_rn(acc[nt][2], acc[nt][3]);
            }
        }
        __syncthreads();
    }
}

// ---------------------------------------------------------------------------
// launch
// ---------------------------------------------------------------------------
extern "C" void kernel_launch(void* const* d_in, const int* in_sizes, int n_in,
                              void* d_out, int out_size) {
    const float* x          = (const float*)d_in[0];
    const float* mask       = (const float*)d_in[1];
    const float* qkv_w      = (const float*)d_in[2];
    const float* qkv_b      = (const float*)d_in[3];
    const float* proj_w     = (const float*)d_in[4];
    const float* proj_b     = (const float*)d_in[5];
    const float* bias_table = (const float*)d_in[6];
    const int*   rel_index  = (const int*)d_in[7];
    float* out = (float*)d_out;

    void* p_qkvh = nullptr; void* p_aoh = nullptr;
    void* p_xh   = nullptr; void* p_wh  = nullptr;
    cudaGetSymbolAddress(&p_qkvh, g_qkvh);
    cudaGetSymbolAddress(&p_aoh,  g_aoh);
    cudaGetSymbolAddress(&p_xh,   g_xh);
    cudaGetSymbolAddress(&p_wh,   g_wh);
    __half* qkvh = (__half*)p_qkvh;
    __half* aoh  = (__half*)p_aoh;
    __half* xh   = (__half*)p_xh;
    __half* qkvw_h  = (__half*)p_wh;
    __half* projw_h = qkvw_h + 3 * DIM * DIM;

    cudaFuncSetAttribute(gemm_f16_pipe<true>,
                         cudaFuncAttributeMaxDynamicSharedMemorySize,
                         GEMM_SMEM_BYTES);
    cudaFuncSetAttribute(gemm_f16_pipe<false>,
                         cudaFuncAttributeMaxDynamicSharedMemorySize,
                         GEMM_SMEM_BYTES);
    cudaFuncSetAttribute(attn_loop_kernel,
                         cudaFuncAttributeMaxDynamicSharedMemorySize,
                         ATTN_SMEM_BYTES);

    f32_to_f16_kernel<<<2048, 256>>>(x, xh, (T_TOT * DIM) / 4);
    f32_to_f16_kernel<<<256, 256>>>(qkv_w, qkvw_h, (3 * DIM * DIM) / 4);
    f32_to_f16_kernel<<<256, 256>>>(proj_w, projw_h, (DIM * DIM) / 4);
    {
        int n = H_HEADS * NW_MASK * NN;
        comb_kernel<<<(n + 255) / 256, 256>>>(bias_table, rel_index, mask);
    }
    // 1) QKV GEMM -> permuted fp16 [3][H][B_][49][32], q pre-scaled
    {
        dim3 grid((3 * DIM) / GBN, T_TOT / GBM);
        gemm_f16_pipe<true><<<grid, 512, GEMM_SMEM_BYTES>>>(
            xh, qkvw_h, qkv_b, qkvh, T_TOT, 3 * DIM, DIM);
    }
    // 2) fused attention: looped windows, double-buffered fill
    {
        dim3 grid(H_HEADS, NW_MASK, B_WIN / NW_MASK / (2 * AITERS));
        attn_loop_kernel<<<grid, 256, ATTN_SMEM_BYTES>>>();
    }
    // 3) proj GEMM: (T,384) @ (384,384)^T -> (T,384) fp32
    {
        dim3 grid(DIM / GBN, T_TOT / GBM);
        gemm_f16_pipe<false><<<grid, 512, GEMM_SMEM_BYTES>>>(
            aoh, projw_h, proj_b, out, T_TOT, DIM, DIM);
    }
}